// round 10
// baseline (speedup 1.0000x reference)
#include <cuda_runtime.h>
#include <cstdint>

#define NUM_USERS 100000
#define NUM_ITEMS 50000
#define N_NODES   150000
#define EMB       64
#define BATCH     16384
#define NNZ_MAX   2400000
#define NB_SCAN   ((N_NODES + 255) / 256)
#define ROWS_PER_BLOCK 32
#define EDGE_CAP  768           // int2 staging cap per block (6 KB smem)

// ---------------- scratch (static device allocations; no cudaMalloc) --------
// NOTE: g_cnt relies on BSS zero-init; scan1_kernel re-zeroes it after use so
// the zero invariant holds for every subsequent launch/graph replay.
__device__ float g_feat1[N_NODES * EMB];
__device__ float g_feat2[N_NODES * EMB];
__device__ int   g_cnt[N_NODES];
__device__ int   g_rowptr[N_NODES + 1];
__device__ int   g_cursor[N_NODES];
__device__ int   g_part[NB_SCAN];
__device__ int2  g_edges[NNZ_MAX];          // sorted-by-row (col, val_bits)

// Split-pointer node row lookup. For layer 2+, pass u=base, i=base+U*64 and
// this reduces to contiguous addressing for every node.
__device__ __forceinline__ const float* node_row(const float* __restrict__ u,
                                                 const float* __restrict__ i,
                                                 int node) {
    return (node < NUM_USERS) ? (u + (size_t)node * EMB)
                              : (i + (size_t)(node - NUM_USERS) * EMB);
}

// ---------------- CSR build: histogram + scan + scatter ---------------------
// 4 edges per thread -> 4 independent atomic chains in flight.
__global__ void hist_kernel(const int* __restrict__ rows, int nnz) {
    int base = blockIdx.x * 1024 + threadIdx.x;
    #pragma unroll
    for (int k = 0; k < 4; k++) {
        int e = base + k * 256;
        if (e < nnz) atomicAdd(&g_cnt[rows[e]], 1);
    }
}

__global__ void scan1_kernel() {
    __shared__ int sm[256];
    int t = threadIdx.x;
    int i = blockIdx.x * 256 + t;
    int c = (i < N_NODES) ? g_cnt[i] : 0;
    if (i < N_NODES) g_cnt[i] = 0;                 // restore zero invariant
    sm[t] = c;
    __syncthreads();
    #pragma unroll
    for (int off = 1; off < 256; off <<= 1) {
        int v = (t >= off) ? sm[t - off] : 0;
        __syncthreads();
        sm[t] += v;
        __syncthreads();
    }
    if (i < N_NODES) g_rowptr[i] = sm[t] - c;      // block-local exclusive
    if (t == 255) g_part[blockIdx.x] = sm[255];    // block total
}

// scan2+scan3 merged: each block computes its own offset = sum(g_part[0..bid))
__global__ void scan23_kernel(int nnz) {
    __shared__ int red[32];
    int t = threadIdx.x;
    int partial = 0;
    for (int j = t; j < blockIdx.x; j += 256) partial += g_part[j];
    #pragma unroll
    for (int off = 16; off > 0; off >>= 1)
        partial += __shfl_xor_sync(0xffffffffu, partial, off);
    if ((t & 31) == 0) red[t >> 5] = partial;
    __syncthreads();
    int offset = red[0] + red[1] + red[2] + red[3] +
                 red[4] + red[5] + red[6] + red[7];
    int i = blockIdx.x * 256 + t;
    if (i < N_NODES) {
        int v = g_rowptr[i] + offset;
        g_rowptr[i] = v;
        g_cursor[i] = v;
    }
    if (i == 0) g_rowptr[N_NODES] = nnz;
}

// 4 edges per thread: 4 independent ATOMG+STG chains in flight.
__global__ void scatter_kernel(const int*   __restrict__ rows,
                               const int*   __restrict__ cols,
                               const float* __restrict__ vals, int nnz) {
    int base = blockIdx.x * 1024 + threadIdx.x;
    int   e[4], r[4], c[4];
    float v[4];
    bool  p[4];
    #pragma unroll
    for (int k = 0; k < 4; k++) {
        e[k] = base + k * 256;
        p[k] = e[k] < nnz;
    }
    #pragma unroll
    for (int k = 0; k < 4; k++) {
        if (p[k]) {
            r[k] = rows[e[k]];
            c[k] = cols[e[k]];
            v[k] = vals[e[k]];
        }
    }
    int pos[4];
    #pragma unroll
    for (int k = 0; k < 4; k++)
        if (p[k]) pos[k] = atomicAdd(&g_cursor[r[k]], 1);
    #pragma unroll
    for (int k = 0; k < 4; k++)
        if (p[k]) g_edges[pos[k]] = make_int2(c[k], __float_as_int(v[k]));
}

// ---------------- fused layer: feat_out = relu((L@x + x) @ W + b) -----------
// x is addressed via (xu, xi) split pointers (layer 1 reads raw embeddings).
// Block stages its contiguous CSR edge segment in smem; warp = 4 rows;
// 8-edge batches; shuffle-GEMM epilogue with float2-packed weights.
__global__ __launch_bounds__(256)
void spmm_gemm_kernel(const float* __restrict__ xu,
                      const float* __restrict__ xi,
                      const float* __restrict__ W,
                      const float* __restrict__ b,
                      float* __restrict__ out, int nrows) {
    __shared__ float2 sW[64 * 32];    // sW[k*32+j] = (W[k][j], W[k][j+32])
    __shared__ float  sb[64];
    __shared__ int2   sE[EDGE_CAP];
    int tid = threadIdx.x;
    #pragma unroll
    for (int i = tid; i < 2048; i += 256) {
        int k = i >> 5, j = i & 31;
        sW[i] = make_float2(W[k * 64 + j], W[k * 64 + j + 32]);
    }
    if (tid < 64) sb[tid] = b[tid];

    int r_base = blockIdx.x * ROWS_PER_BLOCK;
    int r_end  = min(r_base + ROWS_PER_BLOCK, nrows);
    int blk_s  = g_rowptr[r_base];
    int blk_e  = g_rowptr[r_end];
    bool fast  = (blk_e - blk_s) <= EDGE_CAP;
    int stage  = fast ? (blk_e - blk_s) : 0;
    for (int i = tid; i < stage; i += 256) sE[i] = g_edges[blk_s + i];
    __syncthreads();

    int lane = tid & 31;
    int warp = tid >> 5;
    int r0 = r_base + warp * 4;

    float acc0[4], acc1[4];
    #pragma unroll
    for (int rr = 0; rr < 4; rr++) {
        int row = r0 + rr;
        if (row >= nrows) { acc0[rr] = 0.f; acc1[rr] = 0.f; continue; }
        const float* xr = node_row(xu, xi, row);
        float a0 = xr[lane], a1 = xr[lane + 32];           // self loop
        int s = g_rowptr[row] - blk_s, e = g_rowptr[row + 1] - blk_s;
        int i = s;
        if (fast) {
            for (; i + 8 <= e; i += 8) {
                int2 c[8];
                #pragma unroll
                for (int q = 0; q < 8; q++) c[q] = sE[i + q];
                float xs0[8], xs1[8];
                #pragma unroll
                for (int q = 0; q < 8; q++) {
                    const float* xp = node_row(xu, xi, c[q].x);
                    xs0[q] = xp[lane];  xs1[q] = xp[lane + 32];
                }
                #pragma unroll
                for (int q = 0; q < 8; q++) {
                    float v = __int_as_float(c[q].y);
                    a0 += v * xs0[q];  a1 += v * xs1[q];
                }
            }
            for (; i < e; i++) {
                int2 cc = sE[i];
                float v = __int_as_float(cc.y);
                const float* xp = node_row(xu, xi, cc.x);
                a0 += v * xp[lane];
                a1 += v * xp[lane + 32];
            }
        } else {
            for (; i < e; i++) {
                int2 cc = g_edges[blk_s + i];
                float v = __int_as_float(cc.y);
                const float* xp = node_row(xu, xi, cc.x);
                a0 += v * xp[lane];
                a1 += v * xp[lane + 32];
            }
        }
        acc0[rr] = a0; acc1[rr] = a1;
    }

    // GEMM epilogue: out[c] = relu(b[c] + sum_k h[k] * W[k][c])
    float o0[4], o1[4];
    #pragma unroll
    for (int rr = 0; rr < 4; rr++) { o0[rr] = sb[lane]; o1[rr] = sb[lane + 32]; }
    #pragma unroll
    for (int k = 0; k < 32; k++) {
        float2 w = sW[k * 32 + lane];
        #pragma unroll
        for (int rr = 0; rr < 4; rr++) {
            float hk = __shfl_sync(0xffffffffu, acc0[rr], k);
            o0[rr] += hk * w.x;  o1[rr] += hk * w.y;
        }
    }
    #pragma unroll
    for (int k = 0; k < 32; k++) {
        float2 w = sW[(k + 32) * 32 + lane];
        #pragma unroll
        for (int rr = 0; rr < 4; rr++) {
            float hk = __shfl_sync(0xffffffffu, acc1[rr], k);
            o0[rr] += hk * w.x;  o1[rr] += hk * w.y;
        }
    }
    #pragma unroll
    for (int rr = 0; rr < 4; rr++) {
        int row = r0 + rr;
        if (row >= nrows) break;
        float* op = out + (size_t)row * 64;
        op[lane]      = fmaxf(o0[rr], 0.f);
        op[lane + 32] = fmaxf(o1[rr], 0.f);
    }
}

// ---------------- fused gather + 3-layer MLP --------------------------------
__global__ __launch_bounds__(256)
void mlp_fused_kernel(const int*   __restrict__ userIdx,
                      const int*   __restrict__ itemIdx,
                      const float* __restrict__ uEmb,
                      const float* __restrict__ iEmb,
                      const float* __restrict__ W1, const float* __restrict__ b1,
                      const float* __restrict__ W2, const float* __restrict__ b2,
                      const float* __restrict__ W3, const float* __restrict__ b3,
                      float* __restrict__ out) {
    __shared__ float2 sW[64 * 32];    // current W1 segment, paired cols
    __shared__ float  sW2[64 * 32];
    __shared__ float  sb2[32], sW3[32];
    __shared__ float  sb3;

    int tid = threadIdx.x, lane = tid & 31, warp = tid >> 5;
    #pragma unroll
    for (int i = tid; i < 2048; i += 256) sW2[i] = W2[i];
    if (tid < 32) { sb2[tid] = b2[tid]; sW3[tid] = W3[tid]; }
    if (tid == 0) sb3 = b3[0];

    int base = blockIdx.x * 64 + warp * 8;
    int unode[8], inode[8];
    #pragma unroll
    for (int r = 0; r < 8; r++) {
        unode[r] = __ldg(userIdx + base + r);
        inode[r] = __ldg(itemIdx + base + r) + NUM_USERS;
    }

    float bb0 = __ldg(b1 + lane), bb1 = __ldg(b1 + lane + 32);
    float acc0[8], acc1[8];
    #pragma unroll
    for (int r = 0; r < 8; r++) { acc0[r] = bb0; acc1[r] = bb1; }

    #pragma unroll
    for (int kk = 0; kk < 6; kk++) {
        __syncthreads();
        #pragma unroll
        for (int i = tid; i < 2048; i += 256) {
            int k = i >> 5, j = i & 31;
            sW[i] = make_float2(W1[(kk * 64 + k) * 64 + j],
                                W1[(kk * 64 + k) * 64 + j + 32]);
        }
        __syncthreads();

        int seg = (kk < 3) ? kk : kk - 3;

        float a0[8], a1[8];
        #pragma unroll
        for (int r = 0; r < 8; r++) {
            int node = (kk < 3) ? unode[r] : inode[r];
            const float* er;
            if (seg == 0)      er = node_row(uEmb, iEmb, node);
            else if (seg == 1) er = g_feat1 + (size_t)node * 64;
            else               er = g_feat2 + (size_t)node * 64;
            a0[r] = er[lane]; a1[r] = er[lane + 32];
        }
        #pragma unroll
        for (int k = 0; k < 32; k++) {
            float2 w = sW[k * 32 + lane];
            #pragma unroll
            for (int r = 0; r < 8; r++) {
                float hk = __shfl_sync(0xffffffffu, a0[r], k);
                acc0[r] += hk * w.x;  acc1[r] += hk * w.y;
            }
        }
        #pragma unroll
        for (int k = 0; k < 32; k++) {
            float2 w = sW[(k + 32) * 32 + lane];
            #pragma unroll
            for (int r = 0; r < 8; r++) {
                float hk = __shfl_sync(0xffffffffu, a1[r], k);
                acc0[r] += hk * w.x;  acc1[r] += hk * w.y;
            }
        }
    }

    // stages 2+3, in-warp
    #pragma unroll
    for (int r = 0; r < 8; r++) {
        float m0  = fmaxf(acc0[r], 0.f);
        float m1v = fmaxf(acc1[r], 0.f);
        float acc = sb2[lane];                 // lane = output col (0..31)
        #pragma unroll
        for (int k = 0; k < 32; k++) {
            float hk = __shfl_sync(0xffffffffu, m0, k);
            acc += hk * sW2[k * 32 + lane];
        }
        #pragma unroll
        for (int k = 0; k < 32; k++) {
            float hk = __shfl_sync(0xffffffffu, m1v, k);
            acc += hk * sW2[(k + 32) * 32 + lane];
        }
        float p = acc * sW3[lane];             // no ReLU after W2 (matches ref)
        #pragma unroll
        for (int off = 16; off > 0; off >>= 1)
            p += __shfl_xor_sync(0xffffffffu, p, off);
        if (lane == 0) out[base + r] = p + sb3;
    }
}

// ---------------- launch ----------------------------------------------------
extern "C" void kernel_launch(void* const* d_in, const int* in_sizes, int n_in,
                              void* d_out, int out_size) {
    const int*   userIdx = (const int*)  d_in[0];
    const int*   itemIdx = (const int*)  d_in[1];
    const int*   lapRows = (const int*)  d_in[2];
    const int*   lapCols = (const int*)  d_in[3];
    const float* lapVals = (const float*)d_in[4];
    const float* uEmb    = (const float*)d_in[5];
    const float* iEmb    = (const float*)d_in[6];
    const float* gW0     = (const float*)d_in[7];
    const float* gb0     = (const float*)d_in[8];
    const float* gW1     = (const float*)d_in[9];
    const float* gb1     = (const float*)d_in[10];
    const float* W1      = (const float*)d_in[11];
    const float* b1      = (const float*)d_in[12];
    const float* W2      = (const float*)d_in[13];
    const float* b2      = (const float*)d_in[14];
    const float* W3      = (const float*)d_in[15];
    const float* b3      = (const float*)d_in[16];
    float* out = (float*)d_out;

    const int nnz = in_sizes[2];

    float *feat1;
    cudaGetSymbolAddress((void**)&feat1, g_feat1);

    // 1. build CSR (g_cnt is zero on entry; scan1 restores it after reading)
    const int eb4 = (nnz + 1023) / 1024;
    hist_kernel<<<eb4, 256>>>(lapRows, nnz);
    scan1_kernel<<<NB_SCAN, 256>>>();
    scan23_kernel<<<NB_SCAN, 256>>>(nnz);
    scatter_kernel<<<eb4, 256>>>(lapRows, lapCols, lapVals, nnz);

    // 2. fused layers: feat_{k+1} = relu((L @ feat_k + feat_k) @ W + b)
    //    Layer 1 reads raw embeddings via split pointers (no concat pass).
    //    Layer 2 passes (feat1, feat1 + U*64) -> contiguous addressing.
    const int lb = (N_NODES + ROWS_PER_BLOCK - 1) / ROWS_PER_BLOCK;
    spmm_gemm_kernel<<<lb, 256>>>(uEmb, iEmb, gW0, gb0, feat1, N_NODES);
    float *feat2;
    cudaGetSymbolAddress((void**)&feat2, g_feat2);
    spmm_gemm_kernel<<<lb, 256>>>(feat1, feat1 + (size_t)NUM_USERS * EMB,
                                  gW1, gb1, feat2, N_NODES);

    // 3. fused gather + 3-layer MLP (reads embeddings + feat1 + feat2)
    mlp_fused_kernel<<<BATCH / 64, 256>>>(userIdx, itemIdx, uEmb, iEmb,
                                          W1, b1, W2, b2, W3, b3, out);
}

// round 11
// speedup vs baseline: 1.0653x; 1.0653x over previous
#include <cuda_runtime.h>
#include <cstdint>

#define NUM_USERS 100000
#define NUM_ITEMS 50000
#define N_NODES   150000
#define EMB       64
#define BATCH     16384
#define NNZ_MAX   2400000
#define NB_SCAN   ((N_NODES + 255) / 256)
#define ROWS_PER_BLOCK 64
#define EDGE_CAP  1536          // int2 staging cap per block (12 KB smem)

// ---------------- scratch (static device allocations; no cudaMalloc) --------
// NOTE: g_cnt relies on BSS zero-init; scan1_kernel re-zeroes it after use so
// the zero invariant holds for every subsequent launch/graph replay.
__device__ float g_y    [N_NODES * EMB];   // y = x @ W   (current layer)
__device__ float g_feat1[N_NODES * EMB];   // layer-1 output
__device__ float g_feat2[N_NODES * EMB];   // layer-2 output
__device__ int   g_cnt[N_NODES];
__device__ int   g_rowptr[N_NODES + 1];
__device__ int   g_cursor[N_NODES];
__device__ int   g_part[NB_SCAN];
__device__ int2  g_edges[NNZ_MAX];         // sorted-by-row (col, val_bits)

// Split-pointer node row lookup (layer-1 reads raw embeddings; for contiguous
// buffers pass u=base, i=base+U*64).
__device__ __forceinline__ const float* node_row(const float* __restrict__ u,
                                                 const float* __restrict__ i,
                                                 int node) {
    return (node < NUM_USERS) ? (u + (size_t)node * EMB)
                              : (i + (size_t)(node - NUM_USERS) * EMB);
}

// ---------------- CSR build: histogram + scan + scatter (ILP-1, proven) -----
__global__ void hist_kernel(const int* __restrict__ rows, int nnz) {
    int e = blockIdx.x * 256 + threadIdx.x;
    if (e < nnz) atomicAdd(&g_cnt[rows[e]], 1);
}

__global__ void scan1_kernel() {
    __shared__ int sm[256];
    int t = threadIdx.x;
    int i = blockIdx.x * 256 + t;
    int c = (i < N_NODES) ? g_cnt[i] : 0;
    if (i < N_NODES) g_cnt[i] = 0;                 // restore zero invariant
    sm[t] = c;
    __syncthreads();
    #pragma unroll
    for (int off = 1; off < 256; off <<= 1) {
        int v = (t >= off) ? sm[t - off] : 0;
        __syncthreads();
        sm[t] += v;
        __syncthreads();
    }
    if (i < N_NODES) g_rowptr[i] = sm[t] - c;      // block-local exclusive
    if (t == 255) g_part[blockIdx.x] = sm[255];    // block total
}

__global__ void scan23_kernel(int nnz) {
    __shared__ int red[32];
    int t = threadIdx.x;
    int partial = 0;
    for (int j = t; j < blockIdx.x; j += 256) partial += g_part[j];
    #pragma unroll
    for (int off = 16; off > 0; off >>= 1)
        partial += __shfl_xor_sync(0xffffffffu, partial, off);
    if ((t & 31) == 0) red[t >> 5] = partial;
    __syncthreads();
    int offset = red[0] + red[1] + red[2] + red[3] +
                 red[4] + red[5] + red[6] + red[7];
    int i = blockIdx.x * 256 + t;
    if (i < N_NODES) {
        int v = g_rowptr[i] + offset;
        g_rowptr[i] = v;
        g_cursor[i] = v;
    }
    if (i == 0) g_rowptr[N_NODES] = nnz;
}

__global__ void scatter_kernel(const int*   __restrict__ rows,
                               const int*   __restrict__ cols,
                               const float* __restrict__ vals, int nnz) {
    int e = blockIdx.x * 256 + threadIdx.x;
    if (e >= nnz) return;
    int r = rows[e];
    int pos = atomicAdd(&g_cursor[r], 1);
    g_edges[pos] = make_int2(cols[e], __float_as_int(vals[e]));
}

// ---------------- dense GEMM: y = x @ W[64,64]  (no bias, no relu) ----------
// Warp = 8 rows; shuffle-broadcast over k; float2-packed weights in smem.
__global__ __launch_bounds__(256)
void gemm_kernel(const float* __restrict__ xu,
                 const float* __restrict__ xi,
                 const float* __restrict__ W,
                 float* __restrict__ y, int nrows) {
    __shared__ float2 sW[64 * 32];    // sW[k*32+j] = (W[k][j], W[k][j+32])
    int tid = threadIdx.x;
    #pragma unroll
    for (int i = tid; i < 2048; i += 256) {
        int k = i >> 5, j = i & 31;
        sW[i] = make_float2(W[k * 64 + j], W[k * 64 + j + 32]);
    }
    __syncthreads();

    int lane = tid & 31, warp = tid >> 5;
    int base = blockIdx.x * 64 + warp * 8;

    float a0[8], a1[8], o0[8], o1[8];
    #pragma unroll
    for (int r = 0; r < 8; r++) {
        int row = base + r;
        if (row < nrows) {
            const float* xr = node_row(xu, xi, row);
            a0[r] = xr[lane]; a1[r] = xr[lane + 32];
        } else { a0[r] = 0.f; a1[r] = 0.f; }
        o0[r] = 0.f; o1[r] = 0.f;
    }
    #pragma unroll
    for (int k = 0; k < 32; k++) {
        float2 w = sW[k * 32 + lane];
        #pragma unroll
        for (int r = 0; r < 8; r++) {
            float hk = __shfl_sync(0xffffffffu, a0[r], k);
            o0[r] += hk * w.x;  o1[r] += hk * w.y;
        }
    }
    #pragma unroll
    for (int k = 0; k < 32; k++) {
        float2 w = sW[(k + 32) * 32 + lane];
        #pragma unroll
        for (int r = 0; r < 8; r++) {
            float hk = __shfl_sync(0xffffffffu, a1[r], k);
            o0[r] += hk * w.x;  o1[r] += hk * w.y;
        }
    }
    #pragma unroll
    for (int r = 0; r < 8; r++) {
        int row = base + r;
        if (row >= nrows) break;
        float* op = y + (size_t)row * 64;
        op[lane]      = o0[r];
        op[lane + 32] = o1[r];
    }
}

// ---------------- SpMM: out = relu(L @ y + y + b)  (y pre-transformed) ------
// Block = 64 rows; edge segment staged in smem; warp = 8 rows; 8-edge batches;
// no GEMM epilogue — pure gather-accumulate.
__global__ __launch_bounds__(256)
void spmm_relu_kernel(const float* __restrict__ y,
                      const float* __restrict__ b,
                      float* __restrict__ out, int nrows) {
    __shared__ int2  sE[EDGE_CAP];
    __shared__ float sb[64];
    int tid = threadIdx.x;
    if (tid < 64) sb[tid] = b[tid];

    int r_base = blockIdx.x * ROWS_PER_BLOCK;
    int r_end  = min(r_base + ROWS_PER_BLOCK, nrows);
    int blk_s  = g_rowptr[r_base];
    int blk_e  = g_rowptr[r_end];
    bool fast  = (blk_e - blk_s) <= EDGE_CAP;
    int stage  = fast ? (blk_e - blk_s) : 0;
    for (int i = tid; i < stage; i += 256) sE[i] = g_edges[blk_s + i];
    __syncthreads();

    int lane = tid & 31, warp = tid >> 5;
    int r0 = r_base + warp * 8;

    #pragma unroll
    for (int rr = 0; rr < 8; rr++) {
        int row = r0 + rr;
        if (row >= nrows) break;
        const float* yr = y + (size_t)row * 64;
        float a0 = yr[lane]      + sb[lane];        // self loop + bias
        float a1 = yr[lane + 32] + sb[lane + 32];
        int s = g_rowptr[row] - blk_s, e = g_rowptr[row + 1] - blk_s;
        int i = s;
        if (fast) {
            for (; i + 8 <= e; i += 8) {
                int2 c[8];
                #pragma unroll
                for (int q = 0; q < 8; q++) c[q] = sE[i + q];
                float xs0[8], xs1[8];
                #pragma unroll
                for (int q = 0; q < 8; q++) {
                    const float* yp = y + (size_t)c[q].x * 64;
                    xs0[q] = yp[lane];  xs1[q] = yp[lane + 32];
                }
                #pragma unroll
                for (int q = 0; q < 8; q++) {
                    float v = __int_as_float(c[q].y);
                    a0 += v * xs0[q];  a1 += v * xs1[q];
                }
            }
            for (; i < e; i++) {
                int2 cc = sE[i];
                float v = __int_as_float(cc.y);
                const float* yp = y + (size_t)cc.x * 64;
                a0 += v * yp[lane];
                a1 += v * yp[lane + 32];
            }
        } else {
            for (; i < e; i++) {
                int2 cc = g_edges[blk_s + i];
                float v = __int_as_float(cc.y);
                const float* yp = y + (size_t)cc.x * 64;
                a0 += v * yp[lane];
                a1 += v * yp[lane + 32];
            }
        }
        float* op = out + (size_t)row * 64;
        op[lane]      = fmaxf(a0, 0.f);
        op[lane + 32] = fmaxf(a1, 0.f);
    }
}

// ---------------- fused gather + 3-layer MLP --------------------------------
__global__ __launch_bounds__(256)
void mlp_fused_kernel(const int*   __restrict__ userIdx,
                      const int*   __restrict__ itemIdx,
                      const float* __restrict__ uEmb,
                      const float* __restrict__ iEmb,
                      const float* __restrict__ W1, const float* __restrict__ b1,
                      const float* __restrict__ W2, const float* __restrict__ b2,
                      const float* __restrict__ W3, const float* __restrict__ b3,
                      float* __restrict__ out) {
    __shared__ float2 sW[64 * 32];    // current W1 segment, paired cols
    __shared__ float  sW2[64 * 32];
    __shared__ float  sb2[32], sW3[32];
    __shared__ float  sb3;

    int tid = threadIdx.x, lane = tid & 31, warp = tid >> 5;
    #pragma unroll
    for (int i = tid; i < 2048; i += 256) sW2[i] = W2[i];
    if (tid < 32) { sb2[tid] = b2[tid]; sW3[tid] = W3[tid]; }
    if (tid == 0) sb3 = b3[0];

    int base = blockIdx.x * 64 + warp * 8;
    int unode[8], inode[8];
    #pragma unroll
    for (int r = 0; r < 8; r++) {
        unode[r] = __ldg(userIdx + base + r);
        inode[r] = __ldg(itemIdx + base + r) + NUM_USERS;
    }

    float bb0 = __ldg(b1 + lane), bb1 = __ldg(b1 + lane + 32);
    float acc0[8], acc1[8];
    #pragma unroll
    for (int r = 0; r < 8; r++) { acc0[r] = bb0; acc1[r] = bb1; }

    #pragma unroll
    for (int kk = 0; kk < 6; kk++) {
        __syncthreads();
        #pragma unroll
        for (int i = tid; i < 2048; i += 256) {
            int k = i >> 5, j = i & 31;
            sW[i] = make_float2(W1[(kk * 64 + k) * 64 + j],
                                W1[(kk * 64 + k) * 64 + j + 32]);
        }
        __syncthreads();

        int seg = (kk < 3) ? kk : kk - 3;

        float a0[8], a1[8];
        #pragma unroll
        for (int r = 0; r < 8; r++) {
            int node = (kk < 3) ? unode[r] : inode[r];
            const float* er;
            if (seg == 0)      er = node_row(uEmb, iEmb, node);
            else if (seg == 1) er = g_feat1 + (size_t)node * 64;
            else               er = g_feat2 + (size_t)node * 64;
            a0[r] = er[lane]; a1[r] = er[lane + 32];
        }
        #pragma unroll
        for (int k = 0; k < 32; k++) {
            float2 w = sW[k * 32 + lane];
            #pragma unroll
            for (int r = 0; r < 8; r++) {
                float hk = __shfl_sync(0xffffffffu, a0[r], k);
                acc0[r] += hk * w.x;  acc1[r] += hk * w.y;
            }
        }
        #pragma unroll
        for (int k = 0; k < 32; k++) {
            float2 w = sW[(k + 32) * 32 + lane];
            #pragma unroll
            for (int r = 0; r < 8; r++) {
                float hk = __shfl_sync(0xffffffffu, a1[r], k);
                acc0[r] += hk * w.x;  acc1[r] += hk * w.y;
            }
        }
    }

    // stages 2+3, in-warp
    #pragma unroll
    for (int r = 0; r < 8; r++) {
        float m0  = fmaxf(acc0[r], 0.f);
        float m1v = fmaxf(acc1[r], 0.f);
        float acc = sb2[lane];                 // lane = output col (0..31)
        #pragma unroll
        for (int k = 0; k < 32; k++) {
            float hk = __shfl_sync(0xffffffffu, m0, k);
            acc += hk * sW2[k * 32 + lane];
        }
        #pragma unroll
        for (int k = 0; k < 32; k++) {
            float hk = __shfl_sync(0xffffffffu, m1v, k);
            acc += hk * sW2[(k + 32) * 32 + lane];
        }
        float p = acc * sW3[lane];             // no ReLU after W2 (matches ref)
        #pragma unroll
        for (int off = 16; off > 0; off >>= 1)
            p += __shfl_xor_sync(0xffffffffu, p, off);
        if (lane == 0) out[base + r] = p + sb3;
    }
}

// ---------------- launch ----------------------------------------------------
extern "C" void kernel_launch(void* const* d_in, const int* in_sizes, int n_in,
                              void* d_out, int out_size) {
    const int*   userIdx = (const int*)  d_in[0];
    const int*   itemIdx = (const int*)  d_in[1];
    const int*   lapRows = (const int*)  d_in[2];
    const int*   lapCols = (const int*)  d_in[3];
    const float* lapVals = (const float*)d_in[4];
    const float* uEmb    = (const float*)d_in[5];
    const float* iEmb    = (const float*)d_in[6];
    const float* gW0     = (const float*)d_in[7];
    const float* gb0     = (const float*)d_in[8];
    const float* gW1     = (const float*)d_in[9];
    const float* gb1     = (const float*)d_in[10];
    const float* W1      = (const float*)d_in[11];
    const float* b1      = (const float*)d_in[12];
    const float* W2      = (const float*)d_in[13];
    const float* b2      = (const float*)d_in[14];
    const float* W3      = (const float*)d_in[15];
    const float* b3      = (const float*)d_in[16];
    float* out = (float*)d_out;

    const int nnz = in_sizes[2];

    float *y, *feat1, *feat2;
    cudaGetSymbolAddress((void**)&y,     g_y);
    cudaGetSymbolAddress((void**)&feat1, g_feat1);
    cudaGetSymbolAddress((void**)&feat2, g_feat2);

    const int eb  = (nnz + 255) / 256;
    const int nb  = (N_NODES + 63) / 64;

    // CSR build (g_cnt zero on entry; scan1 restores after reading)
    hist_kernel<<<eb, 256>>>(lapRows, nnz);                       // 1
    scan1_kernel<<<NB_SCAN, 256>>>();                             // 2
    scan23_kernel<<<NB_SCAN, 256>>>(nnz);                         // 3

    // layer 1:  y = x@W0 (independent of CSR -> slot 4, gets profiled)
    gemm_kernel<<<nb, 256>>>(uEmb, iEmb, gW0, y, N_NODES);        // 4
    scatter_kernel<<<eb, 256>>>(lapRows, lapCols, lapVals, nnz);  // 5
    //           feat1 = relu(L@y + y + b0)
    spmm_relu_kernel<<<nb, 256>>>(y, gb0, feat1, N_NODES);        // 6

    // layer 2:  y = feat1@W1 ; feat2 = relu(L@y + y + b1)
    gemm_kernel<<<nb, 256>>>(feat1, feat1 + (size_t)NUM_USERS * EMB,
                             gW1, y, N_NODES);                    // 7
    spmm_relu_kernel<<<nb, 256>>>(y, gb1, feat2, N_NODES);        // 8

    // fused gather + 3-layer MLP
    mlp_fused_kernel<<<BATCH / 64, 256>>>(userIdx, itemIdx, uEmb, iEmb,
                                          W1, b1, W2, b2, W3, b3, out); // 9
}

// round 12
// speedup vs baseline: 1.0954x; 1.0283x over previous
#include <cuda_runtime.h>
#include <cstdint>

#define NUM_USERS 100000
#define NUM_ITEMS 50000
#define N_NODES   150000
#define EMB       64
#define BATCH     16384
#define NNZ_MAX   2400000
#define NB_SCAN   ((N_NODES + 255) / 256)
#define ROWS_PER_BLOCK 64
#define EDGE_CAP  1536          // int2 staging cap per block (12 KB smem)

// ---------------- scratch (static device allocations; no cudaMalloc) --------
// NOTE: g_cnt relies on BSS zero-init; scan1_kernel re-zeroes it after use so
// the zero invariant holds for every subsequent launch/graph replay.
__device__ float g_y    [N_NODES * EMB];   // y = x @ W   (current layer)
__device__ float g_feat1[N_NODES * EMB];   // layer-1 output
__device__ float g_feat2[N_NODES * EMB];   // layer-2 output (only gathered rows valid)
__device__ int   g_cnt[N_NODES];
__device__ int   g_rowptr[N_NODES + 1];
__device__ int   g_cursor[N_NODES];
__device__ int   g_part[NB_SCAN];
__device__ int2  g_edges[NNZ_MAX];         // sorted-by-row (col, val_bits)

// Split-pointer node row lookup (layer-1 reads raw embeddings; for contiguous
// buffers pass u=base, i=base+U*64).
__device__ __forceinline__ const float* node_row(const float* __restrict__ u,
                                                 const float* __restrict__ i,
                                                 int node) {
    return (node < NUM_USERS) ? (u + (size_t)node * EMB)
                              : (i + (size_t)(node - NUM_USERS) * EMB);
}

// ---------------- CSR build: histogram + scan + scatter (ILP-1, proven) -----
__global__ void hist_kernel(const int* __restrict__ rows, int nnz) {
    int e = blockIdx.x * 256 + threadIdx.x;
    if (e < nnz) atomicAdd(&g_cnt[rows[e]], 1);
}

__global__ void scan1_kernel() {
    __shared__ int sm[256];
    int t = threadIdx.x;
    int i = blockIdx.x * 256 + t;
    int c = (i < N_NODES) ? g_cnt[i] : 0;
    if (i < N_NODES) g_cnt[i] = 0;                 // restore zero invariant
    sm[t] = c;
    __syncthreads();
    #pragma unroll
    for (int off = 1; off < 256; off <<= 1) {
        int v = (t >= off) ? sm[t - off] : 0;
        __syncthreads();
        sm[t] += v;
        __syncthreads();
    }
    if (i < N_NODES) g_rowptr[i] = sm[t] - c;      // block-local exclusive
    if (t == 255) g_part[blockIdx.x] = sm[255];    // block total
}

__global__ void scan23_kernel(int nnz) {
    __shared__ int red[32];
    int t = threadIdx.x;
    int partial = 0;
    for (int j = t; j < blockIdx.x; j += 256) partial += g_part[j];
    #pragma unroll
    for (int off = 16; off > 0; off >>= 1)
        partial += __shfl_xor_sync(0xffffffffu, partial, off);
    if ((t & 31) == 0) red[t >> 5] = partial;
    __syncthreads();
    int offset = red[0] + red[1] + red[2] + red[3] +
                 red[4] + red[5] + red[6] + red[7];
    int i = blockIdx.x * 256 + t;
    if (i < N_NODES) {
        int v = g_rowptr[i] + offset;
        g_rowptr[i] = v;
        g_cursor[i] = v;
    }
    if (i == 0) g_rowptr[N_NODES] = nnz;
}

__global__ void scatter_kernel(const int*   __restrict__ rows,
                               const int*   __restrict__ cols,
                               const float* __restrict__ vals, int nnz) {
    int e = blockIdx.x * 256 + threadIdx.x;
    if (e >= nnz) return;
    int r = rows[e];
    int pos = atomicAdd(&g_cursor[r], 1);
    g_edges[pos] = make_int2(cols[e], __float_as_int(vals[e]));
}

// ---------------- dense GEMM: y = x @ W[64,64]  (no bias, no relu) ----------
// Warp = 4 rows (low regs -> high occupancy); shuffle-broadcast over k.
__global__ __launch_bounds__(256)
void gemm_kernel(const float* __restrict__ xu,
                 const float* __restrict__ xi,
                 const float* __restrict__ W,
                 float* __restrict__ y, int nrows) {
    __shared__ float2 sW[64 * 32];    // sW[k*32+j] = (W[k][j], W[k][j+32])
    int tid = threadIdx.x;
    #pragma unroll
    for (int i = tid; i < 2048; i += 256) {
        int k = i >> 5, j = i & 31;
        sW[i] = make_float2(W[k * 64 + j], W[k * 64 + j + 32]);
    }
    __syncthreads();

    int lane = tid & 31, warp = tid >> 5;
    int base = blockIdx.x * 32 + warp * 4;

    float a0[4], a1[4], o0[4], o1[4];
    #pragma unroll
    for (int r = 0; r < 4; r++) {
        int row = base + r;
        if (row < nrows) {
            const float* xr = node_row(xu, xi, row);
            a0[r] = xr[lane]; a1[r] = xr[lane + 32];
        } else { a0[r] = 0.f; a1[r] = 0.f; }
        o0[r] = 0.f; o1[r] = 0.f;
    }
    #pragma unroll
    for (int k = 0; k < 32; k++) {
        float2 w = sW[k * 32 + lane];
        #pragma unroll
        for (int r = 0; r < 4; r++) {
            float hk = __shfl_sync(0xffffffffu, a0[r], k);
            o0[r] += hk * w.x;  o1[r] += hk * w.y;
        }
    }
    #pragma unroll
    for (int k = 0; k < 32; k++) {
        float2 w = sW[(k + 32) * 32 + lane];
        #pragma unroll
        for (int r = 0; r < 4; r++) {
            float hk = __shfl_sync(0xffffffffu, a1[r], k);
            o0[r] += hk * w.x;  o1[r] += hk * w.y;
        }
    }
    #pragma unroll
    for (int r = 0; r < 4; r++) {
        int row = base + r;
        if (row >= nrows) break;
        float* op = y + (size_t)row * 64;
        op[lane]      = o0[r];
        op[lane + 32] = o1[r];
    }
}

// ---------------- SpMM (all rows): out = relu(L @ y + y + b) ----------------
// Block = 64 contiguous rows; edge segment staged in smem; warp = 8 rows.
__global__ __launch_bounds__(256)
void spmm_relu_kernel(const float* __restrict__ y,
                      const float* __restrict__ b,
                      float* __restrict__ out, int nrows) {
    __shared__ int2  sE[EDGE_CAP];
    __shared__ float sb[64];
    int tid = threadIdx.x;
    if (tid < 64) sb[tid] = b[tid];

    int r_base = blockIdx.x * ROWS_PER_BLOCK;
    int r_end  = min(r_base + ROWS_PER_BLOCK, nrows);
    int blk_s  = g_rowptr[r_base];
    int blk_e  = g_rowptr[r_end];
    bool fast  = (blk_e - blk_s) <= EDGE_CAP;
    int stage  = fast ? (blk_e - blk_s) : 0;
    for (int i = tid; i < stage; i += 256) sE[i] = g_edges[blk_s + i];
    __syncthreads();

    int lane = tid & 31, warp = tid >> 5;
    int r0 = r_base + warp * 8;

    #pragma unroll
    for (int rr = 0; rr < 8; rr++) {
        int row = r0 + rr;
        if (row >= nrows) break;
        const float* yr = y + (size_t)row * 64;
        float a0 = yr[lane]      + sb[lane];        // self loop + bias
        float a1 = yr[lane + 32] + sb[lane + 32];
        int s = g_rowptr[row] - blk_s, e = g_rowptr[row + 1] - blk_s;
        int i = s;
        if (fast) {
            for (; i + 8 <= e; i += 8) {
                int2 c[8];
                #pragma unroll
                for (int q = 0; q < 8; q++) c[q] = sE[i + q];
                float xs0[8], xs1[8];
                #pragma unroll
                for (int q = 0; q < 8; q++) {
                    const float* yp = y + (size_t)c[q].x * 64;
                    xs0[q] = yp[lane];  xs1[q] = yp[lane + 32];
                }
                #pragma unroll
                for (int q = 0; q < 8; q++) {
                    float v = __int_as_float(c[q].y);
                    a0 += v * xs0[q];  a1 += v * xs1[q];
                }
            }
            for (; i < e; i++) {
                int2 cc = sE[i];
                float v = __int_as_float(cc.y);
                const float* yp = y + (size_t)cc.x * 64;
                a0 += v * yp[lane];
                a1 += v * yp[lane + 32];
            }
        } else {
            for (; i < e; i++) {
                int2 cc = g_edges[blk_s + i];
                float v = __int_as_float(cc.y);
                const float* yp = y + (size_t)cc.x * 64;
                a0 += v * yp[lane];
                a1 += v * yp[lane + 32];
            }
        }
        float* op = out + (size_t)row * 64;
        op[lane]      = fmaxf(a0, 0.f);
        op[lane + 32] = fmaxf(a1, 0.f);
    }
}

// ---------------- SpMM (gathered rows only): layer-2 shortcut ---------------
// feat2 is only read at userIdx / itemIdx+U -> compute exactly those 32768
// rows (duplicates recompute identical values; benign). Edges read from
// global in 8-edge batches. Warp = 8 entries.
__global__ __launch_bounds__(256)
void spmm_relu_idx_kernel(const int*   __restrict__ userIdx,
                          const int*   __restrict__ itemIdx,
                          const float* __restrict__ y,
                          const float* __restrict__ b,
                          float* __restrict__ out) {
    __shared__ float sb[64];
    int tid = threadIdx.x;
    if (tid < 64) sb[tid] = b[tid];
    __syncthreads();

    int lane = tid & 31, warp = tid >> 5;
    int base = blockIdx.x * 64 + warp * 8;     // entry index base (0..32767)

    #pragma unroll
    for (int rr = 0; rr < 8; rr++) {
        int ent = base + rr;
        int row = (ent < BATCH) ? __ldg(userIdx + ent)
                                : (__ldg(itemIdx + ent - BATCH) + NUM_USERS);
        const float* yr = y + (size_t)row * 64;
        float a0 = yr[lane]      + sb[lane];
        float a1 = yr[lane + 32] + sb[lane + 32];
        int s = g_rowptr[row], e = g_rowptr[row + 1];
        int i = s;
        for (; i + 8 <= e; i += 8) {
            int2 c[8];
            #pragma unroll
            for (int q = 0; q < 8; q++) c[q] = g_edges[i + q];
            float xs0[8], xs1[8];
            #pragma unroll
            for (int q = 0; q < 8; q++) {
                const float* yp = y + (size_t)c[q].x * 64;
                xs0[q] = yp[lane];  xs1[q] = yp[lane + 32];
            }
            #pragma unroll
            for (int q = 0; q < 8; q++) {
                float v = __int_as_float(c[q].y);
                a0 += v * xs0[q];  a1 += v * xs1[q];
            }
        }
        for (; i < e; i++) {
            int2 cc = g_edges[i];
            float v = __int_as_float(cc.y);
            const float* yp = y + (size_t)cc.x * 64;
            a0 += v * yp[lane];
            a1 += v * yp[lane + 32];
        }
        float* op = out + (size_t)row * 64;
        op[lane]      = fmaxf(a0, 0.f);
        op[lane + 32] = fmaxf(a1, 0.f);
    }
}

// ---------------- fused gather + 3-layer MLP --------------------------------
__global__ __launch_bounds__(256)
void mlp_fused_kernel(const int*   __restrict__ userIdx,
                      const int*   __restrict__ itemIdx,
                      const float* __restrict__ uEmb,
                      const float* __restrict__ iEmb,
                      const float* __restrict__ W1, const float* __restrict__ b1,
                      const float* __restrict__ W2, const float* __restrict__ b2,
                      const float* __restrict__ W3, const float* __restrict__ b3,
                      float* __restrict__ out) {
    __shared__ float2 sW[64 * 32];    // current W1 segment, paired cols
    __shared__ float  sW2[64 * 32];
    __shared__ float  sb2[32], sW3[32];
    __shared__ float  sb3;

    int tid = threadIdx.x, lane = tid & 31, warp = tid >> 5;
    #pragma unroll
    for (int i = tid; i < 2048; i += 256) sW2[i] = W2[i];
    if (tid < 32) { sb2[tid] = b2[tid]; sW3[tid] = W3[tid]; }
    if (tid == 0) sb3 = b3[0];

    int base = blockIdx.x * 64 + warp * 8;
    int unode[8], inode[8];
    #pragma unroll
    for (int r = 0; r < 8; r++) {
        unode[r] = __ldg(userIdx + base + r);
        inode[r] = __ldg(itemIdx + base + r) + NUM_USERS;
    }

    float bb0 = __ldg(b1 + lane), bb1 = __ldg(b1 + lane + 32);
    float acc0[8], acc1[8];
    #pragma unroll
    for (int r = 0; r < 8; r++) { acc0[r] = bb0; acc1[r] = bb1; }

    #pragma unroll
    for (int kk = 0; kk < 6; kk++) {
        __syncthreads();
        #pragma unroll
        for (int i = tid; i < 2048; i += 256) {
            int k = i >> 5, j = i & 31;
            sW[i] = make_float2(W1[(kk * 64 + k) * 64 + j],
                                W1[(kk * 64 + k) * 64 + j + 32]);
        }
        __syncthreads();

        int seg = (kk < 3) ? kk : kk - 3;

        float a0[8], a1[8];
        #pragma unroll
        for (int r = 0; r < 8; r++) {
            int node = (kk < 3) ? unode[r] : inode[r];
            const float* er;
            if (seg == 0)      er = node_row(uEmb, iEmb, node);
            else if (seg == 1) er = g_feat1 + (size_t)node * 64;
            else               er = g_feat2 + (size_t)node * 64;
            a0[r] = er[lane]; a1[r] = er[lane + 32];
        }
        #pragma unroll
        for (int k = 0; k < 32; k++) {
            float2 w = sW[k * 32 + lane];
            #pragma unroll
            for (int r = 0; r < 8; r++) {
                float hk = __shfl_sync(0xffffffffu, a0[r], k);
                acc0[r] += hk * w.x;  acc1[r] += hk * w.y;
            }
        }
        #pragma unroll
        for (int k = 0; k < 32; k++) {
            float2 w = sW[(k + 32) * 32 + lane];
            #pragma unroll
            for (int r = 0; r < 8; r++) {
                float hk = __shfl_sync(0xffffffffu, a1[r], k);
                acc0[r] += hk * w.x;  acc1[r] += hk * w.y;
            }
        }
    }

    // stages 2+3, in-warp
    #pragma unroll
    for (int r = 0; r < 8; r++) {
        float m0  = fmaxf(acc0[r], 0.f);
        float m1v = fmaxf(acc1[r], 0.f);
        float acc = sb2[lane];                 // lane = output col (0..31)
        #pragma unroll
        for (int k = 0; k < 32; k++) {
            float hk = __shfl_sync(0xffffffffu, m0, k);
            acc += hk * sW2[k * 32 + lane];
        }
        #pragma unroll
        for (int k = 0; k < 32; k++) {
            float hk = __shfl_sync(0xffffffffu, m1v, k);
            acc += hk * sW2[(k + 32) * 32 + lane];
        }
        float p = acc * sW3[lane];             // no ReLU after W2 (matches ref)
        #pragma unroll
        for (int off = 16; off > 0; off >>= 1)
            p += __shfl_xor_sync(0xffffffffu, p, off);
        if (lane == 0) out[base + r] = p + sb3;
    }
}

// ---------------- launch ----------------------------------------------------
extern "C" void kernel_launch(void* const* d_in, const int* in_sizes, int n_in,
                              void* d_out, int out_size) {
    const int*   userIdx = (const int*)  d_in[0];
    const int*   itemIdx = (const int*)  d_in[1];
    const int*   lapRows = (const int*)  d_in[2];
    const int*   lapCols = (const int*)  d_in[3];
    const float* lapVals = (const float*)d_in[4];
    const float* uEmb    = (const float*)d_in[5];
    const float* iEmb    = (const float*)d_in[6];
    const float* gW0     = (const float*)d_in[7];
    const float* gb0     = (const float*)d_in[8];
    const float* gW1     = (const float*)d_in[9];
    const float* gb1     = (const float*)d_in[10];
    const float* W1      = (const float*)d_in[11];
    const float* b1      = (const float*)d_in[12];
    const float* W2      = (const float*)d_in[13];
    const float* b2      = (const float*)d_in[14];
    const float* W3      = (const float*)d_in[15];
    const float* b3      = (const float*)d_in[16];
    float* out = (float*)d_out;

    const int nnz = in_sizes[2];

    float *y, *feat1, *feat2;
    cudaGetSymbolAddress((void**)&y,     g_y);
    cudaGetSymbolAddress((void**)&feat1, g_feat1);
    cudaGetSymbolAddress((void**)&feat2, g_feat2);

    const int eb  = (nnz + 255) / 256;
    const int gb  = (N_NODES + 31) / 32;    // gemm: 32 rows/block
    const int nb  = (N_NODES + 63) / 64;    // spmm: 64 rows/block

    // CSR build (g_cnt zero on entry; scan1 restores after reading)
    hist_kernel<<<eb, 256>>>(lapRows, nnz);                       // 1
    scan1_kernel<<<NB_SCAN, 256>>>();                             // 2
    scan23_kernel<<<NB_SCAN, 256>>>(nnz);                         // 3

    // layer 1:  y = x@W0 (slot 4 -> profiled)
    gemm_kernel<<<gb, 256>>>(uEmb, iEmb, gW0, y, N_NODES);        // 4
    scatter_kernel<<<eb, 256>>>(lapRows, lapCols, lapVals, nnz);  // 5
    spmm_relu_kernel<<<nb, 256>>>(y, gb0, feat1, N_NODES);        // 6

    // layer 2:  y = feat1@W1 ; feat2 = relu(L@y + y + b1) on gathered rows only
    gemm_kernel<<<gb, 256>>>(feat1, feat1 + (size_t)NUM_USERS * EMB,
                             gW1, y, N_NODES);                    // 7
    spmm_relu_idx_kernel<<<(2 * BATCH) / 64, 256>>>(userIdx, itemIdx,
                                                    y, gb1, feat2); // 8

    // fused gather + 3-layer MLP
    mlp_fused_kernel<<<BATCH / 64, 256>>>(userIdx, itemIdx, uEmb, iEmb,
                                          W1, b1, W2, b2, W3, b3, out); // 9
}

// round 13
// speedup vs baseline: 1.1429x; 1.0434x over previous
#include <cuda_runtime.h>
#include <cstdint>

#define NUM_USERS 100000
#define NUM_ITEMS 50000
#define N_NODES   150000
#define EMB       64
#define BATCH     16384
#define NNZ_MAX   2400000
#define NB_SCAN   ((N_NODES + 255) / 256)
#define ROWS_PER_BLOCK 64
#define EDGE_CAP  1536          // int2 staging cap per block (12 KB smem)

typedef unsigned long long u64;

// ---------------- f32x2 packed-math helpers (sm_103a) -----------------------
__device__ __forceinline__ u64 pack2(float lo, float hi) {
    u64 r;
    asm("mov.b64 %0, {%1, %2};" : "=l"(r) : "f"(lo), "f"(hi));
    return r;
}
__device__ __forceinline__ void unpack2(u64 v, float& lo, float& hi) {
    asm("mov.b64 {%0, %1}, %2;" : "=f"(lo), "=f"(hi) : "l"(v));
}
__device__ __forceinline__ u64 fma2(u64 a, u64 b, u64 c) {
    u64 d;
    asm("fma.rn.f32x2 %0, %1, %2, %3;" : "=l"(d) : "l"(a), "l"(b), "l"(c));
    return d;
}

// ---------------- scratch (static device allocations; no cudaMalloc) --------
// NOTE: g_cnt relies on BSS zero-init; scan1_kernel re-zeroes it after use so
// the zero invariant holds for every subsequent launch/graph replay.
__device__ float g_y    [N_NODES * EMB];   // y = x @ W   (current layer)
__device__ float g_feat1[N_NODES * EMB];   // layer-1 output
__device__ float g_feat2[N_NODES * EMB];   // layer-2 output (only gathered rows valid)
__device__ int   g_cnt[N_NODES];
__device__ int   g_rowptr[N_NODES + 1];
__device__ int   g_cursor[N_NODES];
__device__ int   g_part[NB_SCAN];
__device__ int2  g_edges[NNZ_MAX];         // sorted-by-row (col, val_bits)

// Split-pointer node row lookup (layer-1 reads raw embeddings; for contiguous
// buffers pass u=base, i=base+U*64).
__device__ __forceinline__ const float* node_row(const float* __restrict__ u,
                                                 const float* __restrict__ i,
                                                 int node) {
    return (node < NUM_USERS) ? (u + (size_t)node * EMB)
                              : (i + (size_t)(node - NUM_USERS) * EMB);
}

// ---------------- CSR build: histogram + scan + scatter (ILP-1, proven) -----
__global__ void hist_kernel(const int* __restrict__ rows, int nnz) {
    int e = blockIdx.x * 256 + threadIdx.x;
    if (e < nnz) atomicAdd(&g_cnt[rows[e]], 1);
}

__global__ void scan1_kernel() {
    __shared__ int sm[256];
    int t = threadIdx.x;
    int i = blockIdx.x * 256 + t;
    int c = (i < N_NODES) ? g_cnt[i] : 0;
    if (i < N_NODES) g_cnt[i] = 0;                 // restore zero invariant
    sm[t] = c;
    __syncthreads();
    #pragma unroll
    for (int off = 1; off < 256; off <<= 1) {
        int v = (t >= off) ? sm[t - off] : 0;
        __syncthreads();
        sm[t] += v;
        __syncthreads();
    }
    if (i < N_NODES) g_rowptr[i] = sm[t] - c;      // block-local exclusive
    if (t == 255) g_part[blockIdx.x] = sm[255];    // block total
}

__global__ void scan23_kernel(int nnz) {
    __shared__ int red[32];
    int t = threadIdx.x;
    int partial = 0;
    for (int j = t; j < blockIdx.x; j += 256) partial += g_part[j];
    #pragma unroll
    for (int off = 16; off > 0; off >>= 1)
        partial += __shfl_xor_sync(0xffffffffu, partial, off);
    if ((t & 31) == 0) red[t >> 5] = partial;
    __syncthreads();
    int offset = red[0] + red[1] + red[2] + red[3] +
                 red[4] + red[5] + red[6] + red[7];
    int i = blockIdx.x * 256 + t;
    if (i < N_NODES) {
        int v = g_rowptr[i] + offset;
        g_rowptr[i] = v;
        g_cursor[i] = v;
    }
    if (i == 0) g_rowptr[N_NODES] = nnz;
}

__global__ void scatter_kernel(const int*   __restrict__ rows,
                               const int*   __restrict__ cols,
                               const float* __restrict__ vals, int nnz) {
    int e = blockIdx.x * 256 + threadIdx.x;
    if (e >= nnz) return;
    int r = rows[e];
    int pos = atomicAdd(&g_cursor[r], 1);
    g_edges[pos] = make_int2(cols[e], __float_as_int(vals[e]));
}

// ---------------- dense GEMM: y = x @ W[64,64]  (no bias, no relu) ----------
// Block = 64 rows. x staged transposed in smem as row-pairs; inner loop is
// LDS.64 broadcast + packed fma.rn.f32x2 (2 rows per instruction). Warp = 8
// rows (4 pairs), lane = output cols (lane, lane+32).
__global__ __launch_bounds__(256)
void gemm_kernel(const float* __restrict__ xu,
                 const float* __restrict__ xi,
                 const float* __restrict__ W,
                 float* __restrict__ y, int nrows) {
    __shared__ float2 sW[64 * 32];     // sW[k*32+j] = (W[k][j], W[k][j+32])
    __shared__ float2 sXT[64 * 33];    // sXT[k*33+rp] = (x[2rp][k], x[2rp+1][k])
    int tid = threadIdx.x;
    #pragma unroll
    for (int i = tid; i < 2048; i += 256) {
        int k = i >> 5, j = i & 31;
        sW[i] = make_float2(W[k * 64 + j], W[k * 64 + j + 32]);
    }
    int r_base = blockIdx.x * 64;
    #pragma unroll
    for (int i = tid; i < 4096; i += 256) {
        int row = i >> 6, k = i & 63;
        int grow = r_base + row;
        float v = (grow < nrows) ? node_row(xu, xi, grow)[k] : 0.f;
        ((float*)&sXT[k * 33 + (row >> 1)])[row & 1] = v;
    }
    __syncthreads();

    int lane = tid & 31, warp = tid >> 5;
    int rp_base = warp * 4;            // this warp's 4 row-pairs

    u64 po0[4], po1[4];
    #pragma unroll
    for (int rp = 0; rp < 4; rp++) { po0[rp] = 0ull; po1[rp] = 0ull; }

    #pragma unroll 4
    for (int k = 0; k < 64; k++) {
        float2 w = sW[k * 32 + lane];
        u64 wxx = pack2(w.x, w.x);
        u64 wyy = pack2(w.y, w.y);
        #pragma unroll
        for (int rp = 0; rp < 4; rp++) {
            u64 xp = *(const u64*)&sXT[k * 33 + rp_base + rp];
            po0[rp] = fma2(xp, wxx, po0[rp]);
            po1[rp] = fma2(xp, wyy, po1[rp]);
        }
    }

    #pragma unroll
    for (int rp = 0; rp < 4; rp++) {
        int row0 = r_base + warp * 8 + rp * 2;
        float lo0, hi0, lo1, hi1;
        unpack2(po0[rp], lo0, hi0);
        unpack2(po1[rp], lo1, hi1);
        if (row0 < nrows) {
            y[(size_t)row0 * 64 + lane]      = lo0;
            y[(size_t)row0 * 64 + lane + 32] = lo1;
        }
        if (row0 + 1 < nrows) {
            y[(size_t)(row0 + 1) * 64 + lane]      = hi0;
            y[(size_t)(row0 + 1) * 64 + lane + 32] = hi1;
        }
    }
}

// ---------------- SpMM (all rows): out = relu(L @ y + y + b) ----------------
// Block = 64 contiguous rows; edge segment staged in smem; warp = 8 rows.
__global__ __launch_bounds__(256)
void spmm_relu_kernel(const float* __restrict__ y,
                      const float* __restrict__ b,
                      float* __restrict__ out, int nrows) {
    __shared__ int2  sE[EDGE_CAP];
    __shared__ float sb[64];
    int tid = threadIdx.x;
    if (tid < 64) sb[tid] = b[tid];

    int r_base = blockIdx.x * ROWS_PER_BLOCK;
    int r_end  = min(r_base + ROWS_PER_BLOCK, nrows);
    int blk_s  = g_rowptr[r_base];
    int blk_e  = g_rowptr[r_end];
    bool fast  = (blk_e - blk_s) <= EDGE_CAP;
    int stage  = fast ? (blk_e - blk_s) : 0;
    for (int i = tid; i < stage; i += 256) sE[i] = g_edges[blk_s + i];
    __syncthreads();

    int lane = tid & 31, warp = tid >> 5;
    int r0 = r_base + warp * 8;

    #pragma unroll
    for (int rr = 0; rr < 8; rr++) {
        int row = r0 + rr;
        if (row >= nrows) break;
        const float* yr = y + (size_t)row * 64;
        float a0 = yr[lane]      + sb[lane];        // self loop + bias
        float a1 = yr[lane + 32] + sb[lane + 32];
        int s = g_rowptr[row] - blk_s, e = g_rowptr[row + 1] - blk_s;
        int i = s;
        if (fast) {
            for (; i + 8 <= e; i += 8) {
                int2 c[8];
                #pragma unroll
                for (int q = 0; q < 8; q++) c[q] = sE[i + q];
                float xs0[8], xs1[8];
                #pragma unroll
                for (int q = 0; q < 8; q++) {
                    const float* yp = y + (size_t)c[q].x * 64;
                    xs0[q] = yp[lane];  xs1[q] = yp[lane + 32];
                }
                #pragma unroll
                for (int q = 0; q < 8; q++) {
                    float v = __int_as_float(c[q].y);
                    a0 += v * xs0[q];  a1 += v * xs1[q];
                }
            }
            for (; i < e; i++) {
                int2 cc = sE[i];
                float v = __int_as_float(cc.y);
                const float* yp = y + (size_t)cc.x * 64;
                a0 += v * yp[lane];
                a1 += v * yp[lane + 32];
            }
        } else {
            for (; i < e; i++) {
                int2 cc = g_edges[blk_s + i];
                float v = __int_as_float(cc.y);
                const float* yp = y + (size_t)cc.x * 64;
                a0 += v * yp[lane];
                a1 += v * yp[lane + 32];
            }
        }
        float* op = out + (size_t)row * 64;
        op[lane]      = fmaxf(a0, 0.f);
        op[lane + 32] = fmaxf(a1, 0.f);
    }
}

// ---------------- SpMM (gathered rows only): layer-2 shortcut ---------------
// feat2 is only read at userIdx / itemIdx+U -> compute exactly those 32768
// rows (duplicates recompute identical values; benign).
__global__ __launch_bounds__(256)
void spmm_relu_idx_kernel(const int*   __restrict__ userIdx,
                          const int*   __restrict__ itemIdx,
                          const float* __restrict__ y,
                          const float* __restrict__ b,
                          float* __restrict__ out) {
    __shared__ float sb[64];
    int tid = threadIdx.x;
    if (tid < 64) sb[tid] = b[tid];
    __syncthreads();

    int lane = tid & 31, warp = tid >> 5;
    int base = blockIdx.x * 64 + warp * 8;     // entry index base (0..32767)

    #pragma unroll
    for (int rr = 0; rr < 8; rr++) {
        int ent = base + rr;
        int row = (ent < BATCH) ? __ldg(userIdx + ent)
                                : (__ldg(itemIdx + ent - BATCH) + NUM_USERS);
        const float* yr = y + (size_t)row * 64;
        float a0 = yr[lane]      + sb[lane];
        float a1 = yr[lane + 32] + sb[lane + 32];
        int s = g_rowptr[row], e = g_rowptr[row + 1];
        int i = s;
        for (; i + 8 <= e; i += 8) {
            int2 c[8];
            #pragma unroll
            for (int q = 0; q < 8; q++) c[q] = g_edges[i + q];
            float xs0[8], xs1[8];
            #pragma unroll
            for (int q = 0; q < 8; q++) {
                const float* yp = y + (size_t)c[q].x * 64;
                xs0[q] = yp[lane];  xs1[q] = yp[lane + 32];
            }
            #pragma unroll
            for (int q = 0; q < 8; q++) {
                float v = __int_as_float(c[q].y);
                a0 += v * xs0[q];  a1 += v * xs1[q];
            }
        }
        for (; i < e; i++) {
            int2 cc = g_edges[i];
            float v = __int_as_float(cc.y);
            const float* yp = y + (size_t)cc.x * 64;
            a0 += v * yp[lane];
            a1 += v * yp[lane + 32];
        }
        float* op = out + (size_t)row * 64;
        op[lane]      = fmaxf(a0, 0.f);
        op[lane + 32] = fmaxf(a1, 0.f);
    }
}

// ---------------- fused gather + 3-layer MLP --------------------------------
__global__ __launch_bounds__(256)
void mlp_fused_kernel(const int*   __restrict__ userIdx,
                      const int*   __restrict__ itemIdx,
                      const float* __restrict__ uEmb,
                      const float* __restrict__ iEmb,
                      const float* __restrict__ W1, const float* __restrict__ b1,
                      const float* __restrict__ W2, const float* __restrict__ b2,
                      const float* __restrict__ W3, const float* __restrict__ b3,
                      float* __restrict__ out) {
    __shared__ float2 sW[64 * 32];    // current W1 segment, paired cols
    __shared__ float  sW2[64 * 32];
    __shared__ float  sb2[32], sW3[32];
    __shared__ float  sb3;

    int tid = threadIdx.x, lane = tid & 31, warp = tid >> 5;
    #pragma unroll
    for (int i = tid; i < 2048; i += 256) sW2[i] = W2[i];
    if (tid < 32) { sb2[tid] = b2[tid]; sW3[tid] = W3[tid]; }
    if (tid == 0) sb3 = b3[0];

    int base = blockIdx.x * 64 + warp * 8;
    int unode[8], inode[8];
    #pragma unroll
    for (int r = 0; r < 8; r++) {
        unode[r] = __ldg(userIdx + base + r);
        inode[r] = __ldg(itemIdx + base + r) + NUM_USERS;
    }

    float bb0 = __ldg(b1 + lane), bb1 = __ldg(b1 + lane + 32);
    float acc0[8], acc1[8];
    #pragma unroll
    for (int r = 0; r < 8; r++) { acc0[r] = bb0; acc1[r] = bb1; }

    #pragma unroll
    for (int kk = 0; kk < 6; kk++) {
        __syncthreads();
        #pragma unroll
        for (int i = tid; i < 2048; i += 256) {
            int k = i >> 5, j = i & 31;
            sW[i] = make_float2(W1[(kk * 64 + k) * 64 + j],
                                W1[(kk * 64 + k) * 64 + j + 32]);
        }
        __syncthreads();

        int seg = (kk < 3) ? kk : kk - 3;

        float a0[8], a1[8];
        #pragma unroll
        for (int r = 0; r < 8; r++) {
            int node = (kk < 3) ? unode[r] : inode[r];
            const float* er;
            if (seg == 0)      er = node_row(uEmb, iEmb, node);
            else if (seg == 1) er = g_feat1 + (size_t)node * 64;
            else               er = g_feat2 + (size_t)node * 64;
            a0[r] = er[lane]; a1[r] = er[lane + 32];
        }
        #pragma unroll
        for (int k = 0; k < 32; k++) {
            float2 w = sW[k * 32 + lane];
            #pragma unroll
            for (int r = 0; r < 8; r++) {
                float hk = __shfl_sync(0xffffffffu, a0[r], k);
                acc0[r] += hk * w.x;  acc1[r] += hk * w.y;
            }
        }
        #pragma unroll
        for (int k = 0; k < 32; k++) {
            float2 w = sW[(k + 32) * 32 + lane];
            #pragma unroll
            for (int r = 0; r < 8; r++) {
                float hk = __shfl_sync(0xffffffffu, a1[r], k);
                acc0[r] += hk * w.x;  acc1[r] += hk * w.y;
            }
        }
    }

    // stages 2+3, in-warp
    #pragma unroll
    for (int r = 0; r < 8; r++) {
        float m0  = fmaxf(acc0[r], 0.f);
        float m1v = fmaxf(acc1[r], 0.f);
        float acc = sb2[lane];                 // lane = output col (0..31)
        #pragma unroll
        for (int k = 0; k < 32; k++) {
            float hk = __shfl_sync(0xffffffffu, m0, k);
            acc += hk * sW2[k * 32 + lane];
        }
        #pragma unroll
        for (int k = 0; k < 32; k++) {
            float hk = __shfl_sync(0xffffffffu, m1v, k);
            acc += hk * sW2[(k + 32) * 32 + lane];
        }
        float p = acc * sW3[lane];             // no ReLU after W2 (matches ref)
        #pragma unroll
        for (int off = 16; off > 0; off >>= 1)
            p += __shfl_xor_sync(0xffffffffu, p, off);
        if (lane == 0) out[base + r] = p + sb3;
    }
}

// ---------------- launch ----------------------------------------------------
extern "C" void kernel_launch(void* const* d_in, const int* in_sizes, int n_in,
                              void* d_out, int out_size) {
    const int*   userIdx = (const int*)  d_in[0];
    const int*   itemIdx = (const int*)  d_in[1];
    const int*   lapRows = (const int*)  d_in[2];
    const int*   lapCols = (const int*)  d_in[3];
    const float* lapVals = (const float*)d_in[4];
    const float* uEmb    = (const float*)d_in[5];
    const float* iEmb    = (const float*)d_in[6];
    const float* gW0     = (const float*)d_in[7];
    const float* gb0     = (const float*)d_in[8];
    const float* gW1     = (const float*)d_in[9];
    const float* gb1     = (const float*)d_in[10];
    const float* W1      = (const float*)d_in[11];
    const float* b1      = (const float*)d_in[12];
    const float* W2      = (const float*)d_in[13];
    const float* b2      = (const float*)d_in[14];
    const float* W3      = (const float*)d_in[15];
    const float* b3      = (const float*)d_in[16];
    float* out = (float*)d_out;

    const int nnz = in_sizes[2];

    float *y, *feat1, *feat2;
    cudaGetSymbolAddress((void**)&y,     g_y);
    cudaGetSymbolAddress((void**)&feat1, g_feat1);
    cudaGetSymbolAddress((void**)&feat2, g_feat2);

    const int eb  = (nnz + 255) / 256;
    const int gb  = (N_NODES + 63) / 64;    // gemm: 64 rows/block
    const int nb  = (N_NODES + 63) / 64;    // spmm: 64 rows/block

    // CSR build (g_cnt zero on entry; scan1 restores after reading)
    hist_kernel<<<eb, 256>>>(lapRows, nnz);                       // 1
    scan1_kernel<<<NB_SCAN, 256>>>();                             // 2
    scan23_kernel<<<NB_SCAN, 256>>>(nnz);                         // 3

    // layer 1:  y = x@W0 (slot 4 -> profiled)
    gemm_kernel<<<gb, 256>>>(uEmb, iEmb, gW0, y, N_NODES);        // 4
    scatter_kernel<<<eb, 256>>>(lapRows, lapCols, lapVals, nnz);  // 5
    spmm_relu_kernel<<<nb, 256>>>(y, gb0, feat1, N_NODES);        // 6

    // layer 2:  y = feat1@W1 ; feat2 = relu(L@y + y + b1) on gathered rows only
    gemm_kernel<<<gb, 256>>>(feat1, feat1 + (size_t)NUM_USERS * EMB,
                             gW1, y, N_NODES);                    // 7
    spmm_relu_idx_kernel<<<(2 * BATCH) / 64, 256>>>(userIdx, itemIdx,
                                                    y, gb1, feat2); // 8

    // fused gather + 3-layer MLP
    mlp_fused_kernel<<<BATCH / 64, 256>>>(userIdx, itemIdx, uEmb, iEmb,
                                          W1, b1, W2, b2, W3, b3, out); // 9
}

// round 14
// speedup vs baseline: 1.1489x; 1.0052x over previous
#include <cuda_runtime.h>
#include <cstdint>

#define NUM_USERS 100000
#define NUM_ITEMS 50000
#define N_NODES   150000
#define EMB       64
#define BATCH     16384
#define NNZ_MAX   2400000
#define NB_SCAN   ((N_NODES + 255) / 256)
#define ROWS_PER_BLOCK 64
#define EDGE_CAP  1536          // int2 staging cap per block (12 KB smem)
#define GB_BLOCKS ((N_NODES + 63) / 64)   // gemm blocks in the fat kernel

typedef unsigned long long u64;

// ---------------- f32x2 packed-math helpers (sm_103a) -----------------------
__device__ __forceinline__ u64 pack2(float lo, float hi) {
    u64 r;
    asm("mov.b64 %0, {%1, %2};" : "=l"(r) : "f"(lo), "f"(hi));
    return r;
}
__device__ __forceinline__ void unpack2(u64 v, float& lo, float& hi) {
    asm("mov.b64 {%0, %1}, %2;" : "=f"(lo), "=f"(hi) : "l"(v));
}
__device__ __forceinline__ u64 fma2(u64 a, u64 b, u64 c) {
    u64 d;
    asm("fma.rn.f32x2 %0, %1, %2, %3;" : "=l"(d) : "l"(a), "l"(b), "l"(c));
    return d;
}

// ---------------- scratch (static device allocations; no cudaMalloc) --------
// NOTE: g_cnt relies on BSS zero-init; scan1_kernel re-zeroes it after use so
// the zero invariant holds for every subsequent launch/graph replay.
__device__ float g_y    [N_NODES * EMB];   // y = x @ W   (current layer)
__device__ float g_feat1[N_NODES * EMB];   // layer-1 output
__device__ float g_feat2[N_NODES * EMB];   // layer-2 output (only gathered rows valid)
__device__ int   g_cnt[N_NODES];
__device__ int   g_rowptr[N_NODES + 1];
__device__ int   g_cursor[N_NODES];
__device__ int   g_part[NB_SCAN];
__device__ int2  g_edges[NNZ_MAX];         // sorted-by-row (col, val_bits)

// Split-pointer node row lookup (layer-1 reads raw embeddings; for contiguous
// buffers pass u=base, i=base+U*64).
__device__ __forceinline__ const float* node_row(const float* __restrict__ u,
                                                 const float* __restrict__ i,
                                                 int node) {
    return (node < NUM_USERS) ? (u + (size_t)node * EMB)
                              : (i + (size_t)(node - NUM_USERS) * EMB);
}

// ---------------- CSR build: histogram + scan ------------------------------
__global__ void hist_kernel(const int* __restrict__ rows, int nnz) {
    int e = blockIdx.x * 256 + threadIdx.x;
    if (e < nnz) atomicAdd(&g_cnt[rows[e]], 1);
}

__global__ void scan1_kernel() {
    __shared__ int sm[256];
    int t = threadIdx.x;
    int i = blockIdx.x * 256 + t;
    int c = (i < N_NODES) ? g_cnt[i] : 0;
    if (i < N_NODES) g_cnt[i] = 0;                 // restore zero invariant
    sm[t] = c;
    __syncthreads();
    #pragma unroll
    for (int off = 1; off < 256; off <<= 1) {
        int v = (t >= off) ? sm[t - off] : 0;
        __syncthreads();
        sm[t] += v;
        __syncthreads();
    }
    if (i < N_NODES) g_rowptr[i] = sm[t] - c;      // block-local exclusive
    if (t == 255) g_part[blockIdx.x] = sm[255];    // block total
}

__global__ void scan23_kernel(int nnz) {
    __shared__ int red[32];
    int t = threadIdx.x;
    int partial = 0;
    for (int j = t; j < blockIdx.x; j += 256) partial += g_part[j];
    #pragma unroll
    for (int off = 16; off > 0; off >>= 1)
        partial += __shfl_xor_sync(0xffffffffu, partial, off);
    if ((t & 31) == 0) red[t >> 5] = partial;
    __syncthreads();
    int offset = red[0] + red[1] + red[2] + red[3] +
                 red[4] + red[5] + red[6] + red[7];
    int i = blockIdx.x * 256 + t;
    if (i < N_NODES) {
        int v = g_rowptr[i] + offset;
        g_rowptr[i] = v;
        g_cursor[i] = v;
    }
    if (i == 0) g_rowptr[N_NODES] = nnz;
}

// ---------------- FAT kernel: gemm1 (blocks [0,GB)) ∥ scatter (rest) --------
// gemm1 (issue-bound) and scatter (ATOMG-latency-bound, issue ~5%) are
// independent; co-residency lets scatter's stalls be filled by gemm issue.
__global__ __launch_bounds__(256)
void fat_gemm_scatter_kernel(const float* __restrict__ xu,
                             const float* __restrict__ xi,
                             const float* __restrict__ W,
                             float* __restrict__ y, int nrows,
                             const int*   __restrict__ rows,
                             const int*   __restrict__ cols,
                             const float* __restrict__ vals, int nnz) {
    __shared__ float2 sW[64 * 32];     // sW[k*32+j] = (W[k][j], W[k][j+32])
    __shared__ float2 sXT[64 * 33];    // sXT[k*33+rp] = (x[2rp][k], x[2rp+1][k])
    int tid = threadIdx.x;

    if (blockIdx.x >= GB_BLOCKS) {
        // ---- scatter path (no smem, no syncs) ----
        int e = (blockIdx.x - GB_BLOCKS) * 256 + tid;
        if (e < nnz) {
            int r = rows[e];
            int pos = atomicAdd(&g_cursor[r], 1);
            g_edges[pos] = make_int2(cols[e], __float_as_int(vals[e]));
        }
        return;
    }

    // ---- gemm path: y = x @ W for 64 rows ----
    #pragma unroll
    for (int i = tid; i < 2048; i += 256) {
        int k = i >> 5, j = i & 31;
        sW[i] = make_float2(W[k * 64 + j], W[k * 64 + j + 32]);
    }
    int r_base = blockIdx.x * 64;
    #pragma unroll
    for (int i = tid; i < 4096; i += 256) {
        int row = i >> 6, k = i & 63;
        int grow = r_base + row;
        float v = (grow < nrows) ? node_row(xu, xi, grow)[k] : 0.f;
        ((float*)&sXT[k * 33 + (row >> 1)])[row & 1] = v;
    }
    __syncthreads();

    int lane = tid & 31, warp = tid >> 5;
    int rp_base = warp * 4;            // this warp's 4 row-pairs

    u64 po0[4], po1[4];
    #pragma unroll
    for (int rp = 0; rp < 4; rp++) { po0[rp] = 0ull; po1[rp] = 0ull; }

    #pragma unroll 4
    for (int k = 0; k < 64; k++) {
        float2 w = sW[k * 32 + lane];
        u64 wxx = pack2(w.x, w.x);
        u64 wyy = pack2(w.y, w.y);
        #pragma unroll
        for (int rp = 0; rp < 4; rp++) {
            u64 xp = *(const u64*)&sXT[k * 33 + rp_base + rp];
            po0[rp] = fma2(xp, wxx, po0[rp]);
            po1[rp] = fma2(xp, wyy, po1[rp]);
        }
    }

    #pragma unroll
    for (int rp = 0; rp < 4; rp++) {
        int row0 = r_base + warp * 8 + rp * 2;
        float lo0, hi0, lo1, hi1;
        unpack2(po0[rp], lo0, hi0);
        unpack2(po1[rp], lo1, hi1);
        if (row0 < nrows) {
            y[(size_t)row0 * 64 + lane]      = lo0;
            y[(size_t)row0 * 64 + lane + 32] = lo1;
        }
        if (row0 + 1 < nrows) {
            y[(size_t)(row0 + 1) * 64 + lane]      = hi0;
            y[(size_t)(row0 + 1) * 64 + lane + 32] = hi1;
        }
    }
}

// ---------------- dense GEMM (standalone, for layer 2) ----------------------
__global__ __launch_bounds__(256)
void gemm_kernel(const float* __restrict__ xu,
                 const float* __restrict__ xi,
                 const float* __restrict__ W,
                 float* __restrict__ y, int nrows) {
    __shared__ float2 sW[64 * 32];
    __shared__ float2 sXT[64 * 33];
    int tid = threadIdx.x;
    #pragma unroll
    for (int i = tid; i < 2048; i += 256) {
        int k = i >> 5, j = i & 31;
        sW[i] = make_float2(W[k * 64 + j], W[k * 64 + j + 32]);
    }
    int r_base = blockIdx.x * 64;
    #pragma unroll
    for (int i = tid; i < 4096; i += 256) {
        int row = i >> 6, k = i & 63;
        int grow = r_base + row;
        float v = (grow < nrows) ? node_row(xu, xi, grow)[k] : 0.f;
        ((float*)&sXT[k * 33 + (row >> 1)])[row & 1] = v;
    }
    __syncthreads();

    int lane = tid & 31, warp = tid >> 5;
    int rp_base = warp * 4;

    u64 po0[4], po1[4];
    #pragma unroll
    for (int rp = 0; rp < 4; rp++) { po0[rp] = 0ull; po1[rp] = 0ull; }

    #pragma unroll 4
    for (int k = 0; k < 64; k++) {
        float2 w = sW[k * 32 + lane];
        u64 wxx = pack2(w.x, w.x);
        u64 wyy = pack2(w.y, w.y);
        #pragma unroll
        for (int rp = 0; rp < 4; rp++) {
            u64 xp = *(const u64*)&sXT[k * 33 + rp_base + rp];
            po0[rp] = fma2(xp, wxx, po0[rp]);
            po1[rp] = fma2(xp, wyy, po1[rp]);
        }
    }

    #pragma unroll
    for (int rp = 0; rp < 4; rp++) {
        int row0 = r_base + warp * 8 + rp * 2;
        float lo0, hi0, lo1, hi1;
        unpack2(po0[rp], lo0, hi0);
        unpack2(po1[rp], lo1, hi1);
        if (row0 < nrows) {
            y[(size_t)row0 * 64 + lane]      = lo0;
            y[(size_t)row0 * 64 + lane + 32] = lo1;
        }
        if (row0 + 1 < nrows) {
            y[(size_t)(row0 + 1) * 64 + lane]      = hi0;
            y[(size_t)(row0 + 1) * 64 + lane + 32] = hi1;
        }
    }
}

// ---------------- SpMM (all rows): out = relu(L @ y + y + b) ----------------
__global__ __launch_bounds__(256)
void spmm_relu_kernel(const float* __restrict__ y,
                      const float* __restrict__ b,
                      float* __restrict__ out, int nrows) {
    __shared__ int2  sE[EDGE_CAP];
    __shared__ float sb[64];
    int tid = threadIdx.x;
    if (tid < 64) sb[tid] = b[tid];

    int r_base = blockIdx.x * ROWS_PER_BLOCK;
    int r_end  = min(r_base + ROWS_PER_BLOCK, nrows);
    int blk_s  = g_rowptr[r_base];
    int blk_e  = g_rowptr[r_end];
    bool fast  = (blk_e - blk_s) <= EDGE_CAP;
    int stage  = fast ? (blk_e - blk_s) : 0;
    for (int i = tid; i < stage; i += 256) sE[i] = g_edges[blk_s + i];
    __syncthreads();

    int lane = tid & 31, warp = tid >> 5;
    int r0 = r_base + warp * 8;

    #pragma unroll
    for (int rr = 0; rr < 8; rr++) {
        int row = r0 + rr;
        if (row >= nrows) break;
        const float* yr = y + (size_t)row * 64;
        float a0 = yr[lane]      + sb[lane];        // self loop + bias
        float a1 = yr[lane + 32] + sb[lane + 32];
        int s = g_rowptr[row] - blk_s, e = g_rowptr[row + 1] - blk_s;
        int i = s;
        if (fast) {
            for (; i + 8 <= e; i += 8) {
                int2 c[8];
                #pragma unroll
                for (int q = 0; q < 8; q++) c[q] = sE[i + q];
                float xs0[8], xs1[8];
                #pragma unroll
                for (int q = 0; q < 8; q++) {
                    const float* yp = y + (size_t)c[q].x * 64;
                    xs0[q] = yp[lane];  xs1[q] = yp[lane + 32];
                }
                #pragma unroll
                for (int q = 0; q < 8; q++) {
                    float v = __int_as_float(c[q].y);
                    a0 += v * xs0[q];  a1 += v * xs1[q];
                }
            }
            for (; i < e; i++) {
                int2 cc = sE[i];
                float v = __int_as_float(cc.y);
                const float* yp = y + (size_t)cc.x * 64;
                a0 += v * yp[lane];
                a1 += v * yp[lane + 32];
            }
        } else {
            for (; i < e; i++) {
                int2 cc = g_edges[blk_s + i];
                float v = __int_as_float(cc.y);
                const float* yp = y + (size_t)cc.x * 64;
                a0 += v * yp[lane];
                a1 += v * yp[lane + 32];
            }
        }
        float* op = out + (size_t)row * 64;
        op[lane]      = fmaxf(a0, 0.f);
        op[lane + 32] = fmaxf(a1, 0.f);
    }
}

// ---------------- SpMM (gathered rows only): layer-2 shortcut ---------------
__global__ __launch_bounds__(256)
void spmm_relu_idx_kernel(const int*   __restrict__ userIdx,
                          const int*   __restrict__ itemIdx,
                          const float* __restrict__ y,
                          const float* __restrict__ b,
                          float* __restrict__ out) {
    __shared__ float sb[64];
    int tid = threadIdx.x;
    if (tid < 64) sb[tid] = b[tid];
    __syncthreads();

    int lane = tid & 31, warp = tid >> 5;
    int base = blockIdx.x * 64 + warp * 8;     // entry index base (0..32767)

    #pragma unroll
    for (int rr = 0; rr < 8; rr++) {
        int ent = base + rr;
        int row = (ent < BATCH) ? __ldg(userIdx + ent)
                                : (__ldg(itemIdx + ent - BATCH) + NUM_USERS);
        const float* yr = y + (size_t)row * 64;
        float a0 = yr[lane]      + sb[lane];
        float a1 = yr[lane + 32] + sb[lane + 32];
        int s = g_rowptr[row], e = g_rowptr[row + 1];
        int i = s;
        for (; i + 8 <= e; i += 8) {
            int2 c[8];
            #pragma unroll
            for (int q = 0; q < 8; q++) c[q] = g_edges[i + q];
            float xs0[8], xs1[8];
            #pragma unroll
            for (int q = 0; q < 8; q++) {
                const float* yp = y + (size_t)c[q].x * 64;
                xs0[q] = yp[lane];  xs1[q] = yp[lane + 32];
            }
            #pragma unroll
            for (int q = 0; q < 8; q++) {
                float v = __int_as_float(c[q].y);
                a0 += v * xs0[q];  a1 += v * xs1[q];
            }
        }
        for (; i < e; i++) {
            int2 cc = g_edges[i];
            float v = __int_as_float(cc.y);
            const float* yp = y + (size_t)cc.x * 64;
            a0 += v * yp[lane];
            a1 += v * yp[lane + 32];
        }
        float* op = out + (size_t)row * 64;
        op[lane]      = fmaxf(a0, 0.f);
        op[lane + 32] = fmaxf(a1, 0.f);
    }
}

// ---------------- fused gather + 3-layer MLP --------------------------------
__global__ __launch_bounds__(256)
void mlp_fused_kernel(const int*   __restrict__ userIdx,
                      const int*   __restrict__ itemIdx,
                      const float* __restrict__ uEmb,
                      const float* __restrict__ iEmb,
                      const float* __restrict__ W1, const float* __restrict__ b1,
                      const float* __restrict__ W2, const float* __restrict__ b2,
                      const float* __restrict__ W3, const float* __restrict__ b3,
                      float* __restrict__ out) {
    __shared__ float2 sW[64 * 32];    // current W1 segment, paired cols
    __shared__ float  sW2[64 * 32];
    __shared__ float  sb2[32], sW3[32];
    __shared__ float  sb3;

    int tid = threadIdx.x, lane = tid & 31, warp = tid >> 5;
    #pragma unroll
    for (int i = tid; i < 2048; i += 256) sW2[i] = W2[i];
    if (tid < 32) { sb2[tid] = b2[tid]; sW3[tid] = W3[tid]; }
    if (tid == 0) sb3 = b3[0];

    int base = blockIdx.x * 64 + warp * 8;
    int unode[8], inode[8];
    #pragma unroll
    for (int r = 0; r < 8; r++) {
        unode[r] = __ldg(userIdx + base + r);
        inode[r] = __ldg(itemIdx + base + r) + NUM_USERS;
    }

    float bb0 = __ldg(b1 + lane), bb1 = __ldg(b1 + lane + 32);
    float acc0[8], acc1[8];
    #pragma unroll
    for (int r = 0; r < 8; r++) { acc0[r] = bb0; acc1[r] = bb1; }

    #pragma unroll
    for (int kk = 0; kk < 6; kk++) {
        __syncthreads();
        #pragma unroll
        for (int i = tid; i < 2048; i += 256) {
            int k = i >> 5, j = i & 31;
            sW[i] = make_float2(W1[(kk * 64 + k) * 64 + j],
                                W1[(kk * 64 + k) * 64 + j + 32]);
        }
        __syncthreads();

        int seg = (kk < 3) ? kk : kk - 3;

        float a0[8], a1[8];
        #pragma unroll
        for (int r = 0; r < 8; r++) {
            int node = (kk < 3) ? unode[r] : inode[r];
            const float* er;
            if (seg == 0)      er = node_row(uEmb, iEmb, node);
            else if (seg == 1) er = g_feat1 + (size_t)node * 64;
            else               er = g_feat2 + (size_t)node * 64;
            a0[r] = er[lane]; a1[r] = er[lane + 32];
        }
        #pragma unroll
        for (int k = 0; k < 32; k++) {
            float2 w = sW[k * 32 + lane];
            #pragma unroll
            for (int r = 0; r < 8; r++) {
                float hk = __shfl_sync(0xffffffffu, a0[r], k);
                acc0[r] += hk * w.x;  acc1[r] += hk * w.y;
            }
        }
        #pragma unroll
        for (int k = 0; k < 32; k++) {
            float2 w = sW[(k + 32) * 32 + lane];
            #pragma unroll
            for (int r = 0; r < 8; r++) {
                float hk = __shfl_sync(0xffffffffu, a1[r], k);
                acc0[r] += hk * w.x;  acc1[r] += hk * w.y;
            }
        }
    }

    // stages 2+3, in-warp
    #pragma unroll
    for (int r = 0; r < 8; r++) {
        float m0  = fmaxf(acc0[r], 0.f);
        float m1v = fmaxf(acc1[r], 0.f);
        float acc = sb2[lane];                 // lane = output col (0..31)
        #pragma unroll
        for (int k = 0; k < 32; k++) {
            float hk = __shfl_sync(0xffffffffu, m0, k);
            acc += hk * sW2[k * 32 + lane];
        }
        #pragma unroll
        for (int k = 0; k < 32; k++) {
            float hk = __shfl_sync(0xffffffffu, m1v, k);
            acc += hk * sW2[(k + 32) * 32 + lane];
        }
        float p = acc * sW3[lane];             // no ReLU after W2 (matches ref)
        #pragma unroll
        for (int off = 16; off > 0; off >>= 1)
            p += __shfl_xor_sync(0xffffffffu, p, off);
        if (lane == 0) out[base + r] = p + sb3;
    }
}

// ---------------- launch ----------------------------------------------------
extern "C" void kernel_launch(void* const* d_in, const int* in_sizes, int n_in,
                              void* d_out, int out_size) {
    const int*   userIdx = (const int*)  d_in[0];
    const int*   itemIdx = (const int*)  d_in[1];
    const int*   lapRows = (const int*)  d_in[2];
    const int*   lapCols = (const int*)  d_in[3];
    const float* lapVals = (const float*)d_in[4];
    const float* uEmb    = (const float*)d_in[5];
    const float* iEmb    = (const float*)d_in[6];
    const float* gW0     = (const float*)d_in[7];
    const float* gb0     = (const float*)d_in[8];
    const float* gW1     = (const float*)d_in[9];
    const float* gb1     = (const float*)d_in[10];
    const float* W1      = (const float*)d_in[11];
    const float* b1      = (const float*)d_in[12];
    const float* W2      = (const float*)d_in[13];
    const float* b2      = (const float*)d_in[14];
    const float* W3      = (const float*)d_in[15];
    const float* b3      = (const float*)d_in[16];
    float* out = (float*)d_out;

    const int nnz = in_sizes[2];

    float *y, *feat1, *feat2;
    cudaGetSymbolAddress((void**)&y,     g_y);
    cudaGetSymbolAddress((void**)&feat1, g_feat1);
    cudaGetSymbolAddress((void**)&feat2, g_feat2);

    const int eb = (nnz + 255) / 256;
    const int nb = (N_NODES + 63) / 64;

    // CSR front-end (g_cnt zero on entry; scan1 restores after reading)
    hist_kernel<<<eb, 256>>>(lapRows, nnz);                       // 1
    scan1_kernel<<<NB_SCAN, 256>>>();                             // 2
    scan23_kernel<<<NB_SCAN, 256>>>(nnz);                         // 3

    // FAT: gemm1 (y = x@W0) ∥ scatter  (slot 4 -> profiled)
    fat_gemm_scatter_kernel<<<GB_BLOCKS + eb, 256>>>(
        uEmb, iEmb, gW0, y, N_NODES,
        lapRows, lapCols, lapVals, nnz);                          // 4

    // layer 1:  feat1 = relu(L@y + y + b0)
    spmm_relu_kernel<<<nb, 256>>>(y, gb0, feat1, N_NODES);        // 5

    // layer 2:  y = feat1@W1 ; feat2 = relu(L@y + y + b1) on gathered rows only
    gemm_kernel<<<nb, 256>>>(feat1, feat1 + (size_t)NUM_USERS * EMB,
                             gW1, y, N_NODES);                    // 6
    spmm_relu_idx_kernel<<<(2 * BATCH) / 64, 256>>>(userIdx, itemIdx,
                                                    y, gb1, feat2); // 7

    // fused gather + 3-layer MLP
    mlp_fused_kernel<<<BATCH / 64, 256>>>(userIdx, itemIdx, uEmb, iEmb,
                                          W1, b1, W2, b2, W3, b3, out); // 8
}